// round 9
// baseline (speedup 1.0000x reference)
#include <cuda_runtime.h>
#include <cstdint>

// ============================================================================
// KLinear: y = x @ W + bias,  W = (kron(L0,R0)+kron(L1,R1)+kron(L2,R2))/3
// Factorized two-stage GEMMs on mma.sync m16n8k8 tf32 (base ISA).
//   GEMM1: T[(m,a), d] = sum_c x[m, a*C+c] * R[c,d]       (M=2A, N=D, K=C)
//   GEMM2: y[m][b*D+d] += sum_a (L[a,b]/3) * T[(m,a), d]  (per m: M=B, N=D, K=A)
// R9: MT=2 rows/CTA -> smem 103KB -> 2 CTAs/SM (occ 25%->50%); warp blocks 2x2.
// y accumulated in swizzled smem across factors; bias added at epilogue.
// ============================================================================

static constexpr int THREADS = 512;
static constexpr int MT = 2;
static constexpr int NF = 4096;

// SMEM layout (float indices)
static constexpr int YS    = 4352;            // 4096 + 2*(4096/32)
static constexpr int OFF_Y = 0;               // 2 * 4352               = 8704
static constexpr int OFF_T = 8704;            // max MT*A*DP = 256*40   = 10240
static constexpr int OFF_X = 18944;           // max 2A*20 = 256*20     = 5120 (aliased by LT)
static constexpr int OFF_R = 24064;           // 16 * 136               = 2176
static constexpr int SMEM_FLOATS = 26240;
static constexpr int SMEM_BYTES  = SMEM_FLOATS * 4;   // 104960 B

__device__ __forceinline__ uint32_t f2tf(float f) {
    uint32_t r; asm("cvt.rna.tf32.f32 %0, %1;" : "=r"(r) : "f"(f)); return r;
}

__device__ __forceinline__ void mma8(float* c, const uint32_t* a, const uint32_t* b) {
    asm volatile(
        "mma.sync.aligned.m16n8k8.row.col.f32.tf32.tf32.f32 "
        "{%0,%1,%2,%3}, {%4,%5,%6,%7}, {%8,%9}, {%0,%1,%2,%3};"
        : "+f"(c[0]), "+f"(c[1]), "+f"(c[2]), "+f"(c[3])
        : "r"(a[0]), "r"(a[1]), "r"(a[2]), "r"(a[3]), "r"(b[0]), "r"(b[1]));
}

template<int A, int B, int C, int D>
__device__ __forceinline__ void factor(
    const float* __restrict__ x, const float* __restrict__ Lg,
    const float* __restrict__ Rg, float* __restrict__ smem, int m0, int tid)
{
    constexpr int DP  = D + 8;      // padded row stride (R, T)
    constexpr int XS  = 20;         // x chunk row stride (16 + 4)
    constexpr int LTS = 36;         // LT chunk row stride (32 + 4)
    constexpr int NC1 = C / 16;     // K chunks, stage 1
    constexpr int NC2 = A / 32;     // K chunks, stage 2
    constexpr int WG1C = D / 16;    // GEMM1 warp-grid cols (16 warps: (A/16) x (D/16))
    constexpr int WG2C = D / 16;    // GEMM2 warp-grid cols (8 warps/m: (B/32) x (D/16))

    float*    ys  = smem + OFF_Y;
    uint32_t* ts  = (uint32_t*)(smem + OFF_T);
    uint32_t* xs  = (uint32_t*)(smem + OFF_X);
    uint32_t* rs  = (uint32_t*)(smem + OFF_R);
    uint32_t* lts = (uint32_t*)(smem + OFF_X);   // alias (x chunk dead in stage 2)

    const int w    = tid >> 5;
    const int lane = tid & 31;
    const int gid  = lane >> 2;
    const int tig  = lane & 3;

    // ================= GEMM1 =================
    const int wr1 = w / WG1C, wc1 = w % WG1C;
    float accT[2][2][4];
    #pragma unroll
    for (int i = 0; i < 2; i++)
        #pragma unroll
        for (int j = 0; j < 2; j++)
            #pragma unroll
            for (int q = 0; q < 4; q++) accT[i][j][q] = 0.0f;

    for (int ck = 0; ck < NC1; ck++) {
        __syncthreads();   // prev chunk consumed / prev factor fully done

        // ---- x chunk: [2A rows][16 c], tf32, stride 20 ----
        #pragma unroll
        for (int i4 = tid; i4 < MT * A * 4; i4 += THREADS) {
            int r = i4 >> 2, c4 = i4 & 3;
            int m = r / A, a = r % A;
            float4 v = *(const float4*)&x[(size_t)(m0 + m) * NF + a * C + ck * 16 + c4 * 4];
            uint4 u = make_uint4(f2tf(v.x), f2tf(v.y), f2tf(v.z), f2tf(v.w));
            *(uint4*)&xs[r * XS + c4 * 4] = u;
        }
        // ---- R chunk: [16 c][D], tf32, stride DP ----
        #pragma unroll
        for (int i4 = tid; i4 < 16 * (D / 4); i4 += THREADS) {
            int k = i4 / (D / 4), d4 = i4 % (D / 4);
            float4 v = *(const float4*)&Rg[(ck * 16 + k) * D + d4 * 4];
            uint4 u = make_uint4(f2tf(v.x), f2tf(v.y), f2tf(v.z), f2tf(v.w));
            *(uint4*)&rs[k * DP + d4 * 4] = u;
        }
        __syncthreads();

        #pragma unroll
        for (int kt = 0; kt < 2; kt++) {
            uint32_t af[2][4], bf[2][2];
            #pragma unroll
            for (int i = 0; i < 2; i++) {
                int r0 = (wr1 * 2 + i) * 16 + gid;
                af[i][0] = xs[r0 * XS + kt * 8 + tig];
                af[i][1] = xs[(r0 + 8) * XS + kt * 8 + tig];
                af[i][2] = xs[r0 * XS + kt * 8 + tig + 4];
                af[i][3] = xs[(r0 + 8) * XS + kt * 8 + tig + 4];
            }
            #pragma unroll
            for (int j = 0; j < 2; j++) {
                int nc = (wc1 * 2 + j) * 8 + gid;
                bf[j][0] = rs[(kt * 8 + tig) * DP + nc];
                bf[j][1] = rs[(kt * 8 + tig + 4) * DP + nc];
            }
            #pragma unroll
            for (int i = 0; i < 2; i++)
                #pragma unroll
                for (int j = 0; j < 2; j++)
                    mma8(accT[i][j], af[i], bf[j]);
        }
    }

    // ---- store T (tf32) ----
    #pragma unroll
    for (int i = 0; i < 2; i++)
        #pragma unroll
        for (int j = 0; j < 2; j++) {
            int r0 = (wr1 * 2 + i) * 16 + gid;
            int nc = (wc1 * 2 + j) * 8 + 2 * tig;
            uint2 lo = make_uint2(f2tf(accT[i][j][0]), f2tf(accT[i][j][1]));
            uint2 hi = make_uint2(f2tf(accT[i][j][2]), f2tf(accT[i][j][3]));
            *(uint2*)&ts[r0 * DP + nc]       = lo;
            *(uint2*)&ts[(r0 + 8) * DP + nc] = hi;
        }
    __syncthreads();   // T visible; x chunk (lts alias) free to overwrite

    // ================= GEMM2 =================
    const int m   = w >> 3;           // 8 warps per m-row
    const int sw  = w & 7;
    const int wr2 = sw / WG2C, wc2 = sw % WG2C;
    float accY[2][2][4];
    #pragma unroll
    for (int i = 0; i < 2; i++)
        #pragma unroll
        for (int j = 0; j < 2; j++)
            #pragma unroll
            for (int q = 0; q < 4; q++) accY[i][j][q] = 0.0f;

    for (int ac = 0; ac < NC2; ac++) {
        if (ac) __syncthreads();   // protect lts overwrite vs previous mma reads
        // ---- LT chunk: [B][32 a], L transposed, /3, tf32, stride LTS ----
        #pragma unroll
        for (int i = tid; i < 32 * B; i += THREADS) {
            int acx = i / B, b = i % B;
            lts[b * LTS + acx] = f2tf(Lg[(ac * 32 + acx) * B + b] * (1.0f / 3.0f));
        }
        __syncthreads();

        #pragma unroll
        for (int kt = 0; kt < 4; kt++) {
            uint32_t af[2][4], bf[2][2];
            #pragma unroll
            for (int i = 0; i < 2; i++) {
                int rb = (wr2 * 2 + i) * 16 + gid;
                af[i][0] = lts[rb * LTS + kt * 8 + tig];
                af[i][1] = lts[(rb + 8) * LTS + kt * 8 + tig];
                af[i][2] = lts[rb * LTS + kt * 8 + tig + 4];
                af[i][3] = lts[(rb + 8) * LTS + kt * 8 + tig + 4];
            }
            #pragma unroll
            for (int j = 0; j < 2; j++) {
                int nc = (wc2 * 2 + j) * 8 + gid;
                bf[j][0] = ts[(m * A + ac * 32 + kt * 8 + tig) * DP + nc];
                bf[j][1] = ts[(m * A + ac * 32 + kt * 8 + tig + 4) * DP + nc];
            }
            #pragma unroll
            for (int i = 0; i < 2; i++)
                #pragma unroll
                for (int j = 0; j < 2; j++)
                    mma8(accY[i][j], af[i], bf[j]);
        }
    }

    // ---- RMW y (swizzled): ownership disjoint per thread within a factor ----
    #pragma unroll
    for (int i = 0; i < 2; i++)
        #pragma unroll
        for (int j = 0; j < 2; j++) {
            int b = (wr2 * 2 + i) * 16 + gid;
            int d = (wc2 * 2 + j) * 8 + 2 * tig;
            int n0 = b * D + d;
            int s0 = n0 + 2 * (n0 >> 5);
            float2 v0 = *(float2*)&ys[m * YS + s0];
            v0.x += accY[i][j][0]; v0.y += accY[i][j][1];
            *(float2*)&ys[m * YS + s0] = v0;
            int n2 = (b + 8) * D + d;
            int s2 = n2 + 2 * (n2 >> 5);
            float2 v2 = *(float2*)&ys[m * YS + s2];
            v2.x += accY[i][j][2]; v2.y += accY[i][j][3];
            *(float2*)&ys[m * YS + s2] = v2;
        }
}

__global__ __launch_bounds__(THREADS, 2) void klinear_kernel(
    const float* __restrict__ x,
    const float* __restrict__ L0, const float* __restrict__ R0,
    const float* __restrict__ L1, const float* __restrict__ R1,
    const float* __restrict__ L2, const float* __restrict__ R2,
    const float* __restrict__ bias,
    float* __restrict__ out)
{
    extern __shared__ float smem[];
    const int tid = threadIdx.x;
    const int m0  = blockIdx.x * MT;

    // zero y accumulator (bias added in epilogue)
    for (int i = tid; i < MT * YS; i += THREADS)
        smem[OFF_Y + i] = 0.0f;
    // (first factor's chunk-top __syncthreads orders this before any use)

    factor< 64,  64,  64,  64>(x, L0, R0, smem, m0, tid);
    factor< 32,  32, 128, 128>(x, L1, R1, smem, m0, tid);
    factor<128, 128,  32,  32>(x, L2, R2, smem, m0, tid);

    __syncthreads();

    // epilogue: y + bias -> out; thread owns n in [8*tid, 8*tid+8)
    const int n0 = tid * 8;
    const int s  = n0 + 2 * (n0 >> 5);   // contiguous within the 8-run
    float4 b0 = *(const float4*)&bias[n0];
    float4 b1 = *(const float4*)&bias[n0 + 4];
    #pragma unroll
    for (int m = 0; m < MT; m++) {
        const float* yr = smem + OFF_Y + m * YS + s;
        float2 p0 = *(const float2*)&yr[0];
        float2 p1 = *(const float2*)&yr[2];
        float2 p2 = *(const float2*)&yr[4];
        float2 p3 = *(const float2*)&yr[6];
        float4 o0 = make_float4(p0.x + b0.x, p0.y + b0.y, p1.x + b0.z, p1.y + b0.w);
        float4 o1 = make_float4(p2.x + b1.x, p2.y + b1.y, p3.x + b1.z, p3.y + b1.w);
        *(float4*)&out[(size_t)(m0 + m) * NF + n0]     = o0;
        *(float4*)&out[(size_t)(m0 + m) * NF + n0 + 4] = o1;
    }
}

extern "C" void kernel_launch(void* const* d_in, const int* in_sizes, int n_in,
                              void* d_out, int out_size)
{
    const float* x    = (const float*)d_in[0];
    const float* L0   = (const float*)d_in[1];
    const float* R0   = (const float*)d_in[2];
    const float* L1   = (const float*)d_in[3];
    const float* R1   = (const float*)d_in[4];
    const float* L2   = (const float*)d_in[5];
    const float* R2   = (const float*)d_in[6];
    const float* bias = (const float*)d_in[7];
    float* out = (float*)d_out;

    static bool attr_set = false;
    if (!attr_set) {
        cudaFuncSetAttribute(klinear_kernel,
                             cudaFuncAttributeMaxDynamicSharedMemorySize, SMEM_BYTES);
        attr_set = true;
    }

    klinear_kernel<<<16384 / MT, THREADS, SMEM_BYTES>>>(
        x, L0, R0, L1, R1, L2, R2, bias, out);
}

// round 10
// speedup vs baseline: 1.0014x; 1.0014x over previous
#include <cuda_runtime.h>
#include <cstdint>

// ============================================================================
// KLinear: y = x @ W + bias,  W = (kron(L0,R0)+kron(L1,R1)+kron(L2,R2))/3
// Factorized two-stage GEMMs on mma.sync m16n8k8 tf32 (base ISA).
//   GEMM1: T[(m,a), d] = sum_c x[m, a*C+c] * R[c,d]       (M=2A, N=D, K=C)
//   GEMM2: y[m][b*D+d] += sum_a (L[a,b]/3) * T[(m,a), d]  (per m: M=B, N=D, K=A)
// R9: MT=2 rows/CTA -> smem 103KB -> 2 CTAs/SM (occ 25%->50%); warp blocks 2x2.
// y accumulated in swizzled smem across factors; bias added at epilogue.
// ============================================================================

static constexpr int THREADS = 512;
static constexpr int MT = 2;
static constexpr int NF = 4096;

// SMEM layout (float indices)
static constexpr int YS    = 4352;            // 4096 + 2*(4096/32)
static constexpr int OFF_Y = 0;               // 2 * 4352               = 8704
static constexpr int OFF_T = 8704;            // max MT*A*DP = 256*40   = 10240
static constexpr int OFF_X = 18944;           // max 2A*20 = 256*20     = 5120 (aliased by LT)
static constexpr int OFF_R = 24064;           // 16 * 136               = 2176
static constexpr int SMEM_FLOATS = 26240;
static constexpr int SMEM_BYTES  = SMEM_FLOATS * 4;   // 104960 B

__device__ __forceinline__ uint32_t f2tf(float f) {
    uint32_t r; asm("cvt.rna.tf32.f32 %0, %1;" : "=r"(r) : "f"(f)); return r;
}

__device__ __forceinline__ void mma8(float* c, const uint32_t* a, const uint32_t* b) {
    asm volatile(
        "mma.sync.aligned.m16n8k8.row.col.f32.tf32.tf32.f32 "
        "{%0,%1,%2,%3}, {%4,%5,%6,%7}, {%8,%9}, {%0,%1,%2,%3};"
        : "+f"(c[0]), "+f"(c[1]), "+f"(c[2]), "+f"(c[3])
        : "r"(a[0]), "r"(a[1]), "r"(a[2]), "r"(a[3]), "r"(b[0]), "r"(b[1]));
}

template<int A, int B, int C, int D>
__device__ __forceinline__ void factor(
    const float* __restrict__ x, const float* __restrict__ Lg,
    const float* __restrict__ Rg, float* __restrict__ smem, int m0, int tid)
{
    constexpr int DP  = D + 8;      // padded row stride (R, T)
    constexpr int XS  = 20;         // x chunk row stride (16 + 4)
    constexpr int LTS = 36;         // LT chunk row stride (32 + 4)
    constexpr int NC1 = C / 16;     // K chunks, stage 1
    constexpr int NC2 = A / 32;     // K chunks, stage 2
    constexpr int WG1C = D / 16;    // GEMM1 warp-grid cols (16 warps: (A/16) x (D/16))
    constexpr int WG2C = D / 16;    // GEMM2 warp-grid cols (8 warps/m: (B/32) x (D/16))

    float*    ys  = smem + OFF_Y;
    uint32_t* ts  = (uint32_t*)(smem + OFF_T);
    uint32_t* xs  = (uint32_t*)(smem + OFF_X);
    uint32_t* rs  = (uint32_t*)(smem + OFF_R);
    uint32_t* lts = (uint32_t*)(smem + OFF_X);   // alias (x chunk dead in stage 2)

    const int w    = tid >> 5;
    const int lane = tid & 31;
    const int gid  = lane >> 2;
    const int tig  = lane & 3;

    // ================= GEMM1 =================
    const int wr1 = w / WG1C, wc1 = w % WG1C;
    float accT[2][2][4];
    #pragma unroll
    for (int i = 0; i < 2; i++)
        #pragma unroll
        for (int j = 0; j < 2; j++)
            #pragma unroll
            for (int q = 0; q < 4; q++) accT[i][j][q] = 0.0f;

    for (int ck = 0; ck < NC1; ck++) {
        __syncthreads();   // prev chunk consumed / prev factor fully done

        // ---- x chunk: [2A rows][16 c], tf32, stride 20 ----
        #pragma unroll
        for (int i4 = tid; i4 < MT * A * 4; i4 += THREADS) {
            int r = i4 >> 2, c4 = i4 & 3;
            int m = r / A, a = r % A;
            float4 v = *(const float4*)&x[(size_t)(m0 + m) * NF + a * C + ck * 16 + c4 * 4];
            uint4 u = make_uint4(f2tf(v.x), f2tf(v.y), f2tf(v.z), f2tf(v.w));
            *(uint4*)&xs[r * XS + c4 * 4] = u;
        }
        // ---- R chunk: [16 c][D], tf32, stride DP ----
        #pragma unroll
        for (int i4 = tid; i4 < 16 * (D / 4); i4 += THREADS) {
            int k = i4 / (D / 4), d4 = i4 % (D / 4);
            float4 v = *(const float4*)&Rg[(ck * 16 + k) * D + d4 * 4];
            uint4 u = make_uint4(f2tf(v.x), f2tf(v.y), f2tf(v.z), f2tf(v.w));
            *(uint4*)&rs[k * DP + d4 * 4] = u;
        }
        __syncthreads();

        #pragma unroll
        for (int kt = 0; kt < 2; kt++) {
            uint32_t af[2][4], bf[2][2];
            #pragma unroll
            for (int i = 0; i < 2; i++) {
                int r0 = (wr1 * 2 + i) * 16 + gid;
                af[i][0] = xs[r0 * XS + kt * 8 + tig];
                af[i][1] = xs[(r0 + 8) * XS + kt * 8 + tig];
                af[i][2] = xs[r0 * XS + kt * 8 + tig + 4];
                af[i][3] = xs[(r0 + 8) * XS + kt * 8 + tig + 4];
            }
            #pragma unroll
            for (int j = 0; j < 2; j++) {
                int nc = (wc1 * 2 + j) * 8 + gid;
                bf[j][0] = rs[(kt * 8 + tig) * DP + nc];
                bf[j][1] = rs[(kt * 8 + tig + 4) * DP + nc];
            }
            #pragma unroll
            for (int i = 0; i < 2; i++)
                #pragma unroll
                for (int j = 0; j < 2; j++)
                    mma8(accT[i][j], af[i], bf[j]);
        }
    }

    // ---- store T (tf32) ----
    #pragma unroll
    for (int i = 0; i < 2; i++)
        #pragma unroll
        for (int j = 0; j < 2; j++) {
            int r0 = (wr1 * 2 + i) * 16 + gid;
            int nc = (wc1 * 2 + j) * 8 + 2 * tig;
            uint2 lo = make_uint2(f2tf(accT[i][j][0]), f2tf(accT[i][j][1]));
            uint2 hi = make_uint2(f2tf(accT[i][j][2]), f2tf(accT[i][j][3]));
            *(uint2*)&ts[r0 * DP + nc]       = lo;
            *(uint2*)&ts[(r0 + 8) * DP + nc] = hi;
        }
    __syncthreads();   // T visible; x chunk (lts alias) free to overwrite

    // ================= GEMM2 =================
    const int m   = w >> 3;           // 8 warps per m-row
    const int sw  = w & 7;
    const int wr2 = sw / WG2C, wc2 = sw % WG2C;
    float accY[2][2][4];
    #pragma unroll
    for (int i = 0; i < 2; i++)
        #pragma unroll
        for (int j = 0; j < 2; j++)
            #pragma unroll
            for (int q = 0; q < 4; q++) accY[i][j][q] = 0.0f;

    for (int ac = 0; ac < NC2; ac++) {
        if (ac) __syncthreads();   // protect lts overwrite vs previous mma reads
        // ---- LT chunk: [B][32 a], L transposed, /3, tf32, stride LTS ----
        #pragma unroll
        for (int i = tid; i < 32 * B; i += THREADS) {
            int acx = i / B, b = i % B;
            lts[b * LTS + acx] = f2tf(Lg[(ac * 32 + acx) * B + b] * (1.0f / 3.0f));
        }
        __syncthreads();

        #pragma unroll
        for (int kt = 0; kt < 4; kt++) {
            uint32_t af[2][4], bf[2][2];
            #pragma unroll
            for (int i = 0; i < 2; i++) {
                int rb = (wr2 * 2 + i) * 16 + gid;
                af[i][0] = lts[rb * LTS + kt * 8 + tig];
                af[i][1] = lts[(rb + 8) * LTS + kt * 8 + tig];
                af[i][2] = lts[rb * LTS + kt * 8 + tig + 4];
                af[i][3] = lts[(rb + 8) * LTS + kt * 8 + tig + 4];
            }
            #pragma unroll
            for (int j = 0; j < 2; j++) {
                int nc = (wc2 * 2 + j) * 8 + gid;
                bf[j][0] = ts[(m * A + ac * 32 + kt * 8 + tig) * DP + nc];
                bf[j][1] = ts[(m * A + ac * 32 + kt * 8 + tig + 4) * DP + nc];
            }
            #pragma unroll
            for (int i = 0; i < 2; i++)
                #pragma unroll
                for (int j = 0; j < 2; j++)
                    mma8(accY[i][j], af[i], bf[j]);
        }
    }

    // ---- RMW y (swizzled): ownership disjoint per thread within a factor ----
    #pragma unroll
    for (int i = 0; i < 2; i++)
        #pragma unroll
        for (int j = 0; j < 2; j++) {
            int b = (wr2 * 2 + i) * 16 + gid;
            int d = (wc2 * 2 + j) * 8 + 2 * tig;
            int n0 = b * D + d;
            int s0 = n0 + 2 * (n0 >> 5);
            float2 v0 = *(float2*)&ys[m * YS + s0];
            v0.x += accY[i][j][0]; v0.y += accY[i][j][1];
            *(float2*)&ys[m * YS + s0] = v0;
            int n2 = (b + 8) * D + d;
            int s2 = n2 + 2 * (n2 >> 5);
            float2 v2 = *(float2*)&ys[m * YS + s2];
            v2.x += accY[i][j][2]; v2.y += accY[i][j][3];
            *(float2*)&ys[m * YS + s2] = v2;
        }
}

__global__ __launch_bounds__(THREADS, 2) void klinear_kernel(
    const float* __restrict__ x,
    const float* __restrict__ L0, const float* __restrict__ R0,
    const float* __restrict__ L1, const float* __restrict__ R1,
    const float* __restrict__ L2, const float* __restrict__ R2,
    const float* __restrict__ bias,
    float* __restrict__ out)
{
    extern __shared__ float smem[];
    const int tid = threadIdx.x;
    const int m0  = blockIdx.x * MT;

    // zero y accumulator (bias added in epilogue)
    for (int i = tid; i < MT * YS; i += THREADS)
        smem[OFF_Y + i] = 0.0f;
    // (first factor's chunk-top __syncthreads orders this before any use)

    factor< 64,  64,  64,  64>(x, L0, R0, smem, m0, tid);
    factor< 32,  32, 128, 128>(x, L1, R1, smem, m0, tid);
    factor<128, 128,  32,  32>(x, L2, R2, smem, m0, tid);

    __syncthreads();

    // epilogue: y + bias -> out; thread owns n in [8*tid, 8*tid+8)
    const int n0 = tid * 8;
    const int s  = n0 + 2 * (n0 >> 5);   // contiguous within the 8-run
    float4 b0 = *(const float4*)&bias[n0];
    float4 b1 = *(const float4*)&bias[n0 + 4];
    #pragma unroll
    for (int m = 0; m < MT; m++) {
        const float* yr = smem + OFF_Y + m * YS + s;
        float2 p0 = *(const float2*)&yr[0];
        float2 p1 = *(const float2*)&yr[2];
        float2 p2 = *(const float2*)&yr[4];
        float2 p3 = *(const float2*)&yr[6];
        float4 o0 = make_float4(p0.x + b0.x, p0.y + b0.y, p1.x + b0.z, p1.y + b0.w);
        float4 o1 = make_float4(p2.x + b1.x, p2.y + b1.y, p3.x + b1.z, p3.y + b1.w);
        *(float4*)&out[(size_t)(m0 + m) * NF + n0]     = o0;
        *(float4*)&out[(size_t)(m0 + m) * NF + n0 + 4] = o1;
    }
}

extern "C" void kernel_launch(void* const* d_in, const int* in_sizes, int n_in,
                              void* d_out, int out_size)
{
    const float* x    = (const float*)d_in[0];
    const float* L0   = (const float*)d_in[1];
    const float* R0   = (const float*)d_in[2];
    const float* L1   = (const float*)d_in[3];
    const float* R1   = (const float*)d_in[4];
    const float* L2   = (const float*)d_in[5];
    const float* R2   = (const float*)d_in[6];
    const float* bias = (const float*)d_in[7];
    float* out = (float*)d_out;

    static bool attr_set = false;
    if (!attr_set) {
        cudaFuncSetAttribute(klinear_kernel,
                             cudaFuncAttributeMaxDynamicSharedMemorySize, SMEM_BYTES);
        attr_set = true;
    }

    klinear_kernel<<<16384 / MT, THREADS, SMEM_BYTES>>>(
        x, L0, R0, L1, R1, L2, R2, bias, out);
}

// round 11
// speedup vs baseline: 1.0593x; 1.0578x over previous
#include <cuda_runtime.h>
#include <cstdint>

// ============================================================================
// KLinear: y = x @ W + bias,  W = (kron(L0,R0)+kron(L1,R1)+kron(L2,R2))/3
// Factorized two-stage GEMMs on mma.sync m16n8k8 tf32 (base ISA).
//   GEMM1: T[(m,a), d] = sum_c x[m, a*C+c] * R[c,d]       (M=2A, N=D, K=C)
//   GEMM2: y[m][b*D+d] += sum_a (L[a,b]/3) * T[(m,a), d]  (per m: M=B, N=D, K=A)
// R11: 256 threads / 8 warps, MT=2, warp blocks 2x4 tiles (0.25 B/MAC fragment
// traffic, as R8) AND 2 CTAs/SM (as R9) — best of both rounds.
// ============================================================================

static constexpr int THREADS = 256;
static constexpr int MT = 2;
static constexpr int NF = 4096;

// SMEM layout (float indices)
static constexpr int YS    = 4352;            // 4096 + 2*(4096/32)
static constexpr int OFF_Y = 0;               // 2 * 4352               = 8704
static constexpr int OFF_T = 8704;            // max MT*A*DP = 256*40   = 10240
static constexpr int OFF_X = 18944;           // max 2A*20 = 256*20     = 5120 (aliased by LT)
static constexpr int OFF_R = 24064;           // 16 * 136               = 2176
static constexpr int SMEM_FLOATS = 26240;
static constexpr int SMEM_BYTES  = SMEM_FLOATS * 4;   // 104960 B

__device__ __forceinline__ uint32_t f2tf(float f) {
    uint32_t r; asm("cvt.rna.tf32.f32 %0, %1;" : "=r"(r) : "f"(f)); return r;
}

__device__ __forceinline__ void mma8(float* c, const uint32_t* a, const uint32_t* b) {
    asm volatile(
        "mma.sync.aligned.m16n8k8.row.col.f32.tf32.tf32.f32 "
        "{%0,%1,%2,%3}, {%4,%5,%6,%7}, {%8,%9}, {%0,%1,%2,%3};"
        : "+f"(c[0]), "+f"(c[1]), "+f"(c[2]), "+f"(c[3])
        : "r"(a[0]), "r"(a[1]), "r"(a[2]), "r"(a[3]), "r"(b[0]), "r"(b[1]));
}

template<int A, int B, int C, int D>
__device__ __forceinline__ void factor(
    const float* __restrict__ x, const float* __restrict__ Lg,
    const float* __restrict__ Rg, float* __restrict__ smem, int m0, int tid)
{
    constexpr int DP  = D + 8;      // padded row stride (R, T)
    constexpr int XS  = 20;         // x chunk row stride (16 + 4)
    constexpr int LTS = 36;         // LT chunk row stride (32 + 4)
    constexpr int NC1 = C / 16;     // K chunks, stage 1
    constexpr int NC2 = A / 32;     // K chunks, stage 2
    // GEMM1: (2A/16) x (D/8) tiles, warp block 2x4 -> grid (A/16) x (D/32), 8 warps
    constexpr int GC1 = D / 32;
    // GEMM2 per m: (B/16) x (D/8) tiles, warp block 2x4 -> grid (B/32) x (D/32), 4 warps
    constexpr int GC2 = D / 32;

    float*    ys  = smem + OFF_Y;
    uint32_t* ts  = (uint32_t*)(smem + OFF_T);
    uint32_t* xs  = (uint32_t*)(smem + OFF_X);
    uint32_t* rs  = (uint32_t*)(smem + OFF_R);
    uint32_t* lts = (uint32_t*)(smem + OFF_X);   // alias (x chunk dead in stage 2)

    const int w    = tid >> 5;
    const int lane = tid & 31;
    const int gid  = lane >> 2;
    const int tig  = lane & 3;

    // ================= GEMM1 =================
    const int wr1 = w / GC1, wc1 = w % GC1;
    float accT[2][4][4];
    #pragma unroll
    for (int i = 0; i < 2; i++)
        #pragma unroll
        for (int j = 0; j < 4; j++)
            #pragma unroll
            for (int q = 0; q < 4; q++) accT[i][j][q] = 0.0f;

    for (int ck = 0; ck < NC1; ck++) {
        __syncthreads();   // prev chunk consumed / prev factor fully done

        // ---- x chunk: [2A rows][16 c], tf32, stride 20 ----
        #pragma unroll
        for (int i4 = tid; i4 < MT * A * 4; i4 += THREADS) {
            int r = i4 >> 2, c4 = i4 & 3;
            int m = r / A, a = r % A;
            float4 v = *(const float4*)&x[(size_t)(m0 + m) * NF + a * C + ck * 16 + c4 * 4];
            uint4 u = make_uint4(f2tf(v.x), f2tf(v.y), f2tf(v.z), f2tf(v.w));
            *(uint4*)&xs[r * XS + c4 * 4] = u;
        }
        // ---- R chunk: [16 c][D], tf32, stride DP ----
        #pragma unroll
        for (int i4 = tid; i4 < 16 * (D / 4); i4 += THREADS) {
            int k = i4 / (D / 4), d4 = i4 % (D / 4);
            float4 v = *(const float4*)&Rg[(ck * 16 + k) * D + d4 * 4];
            uint4 u = make_uint4(f2tf(v.x), f2tf(v.y), f2tf(v.z), f2tf(v.w));
            *(uint4*)&rs[k * DP + d4 * 4] = u;
        }
        __syncthreads();

        #pragma unroll
        for (int kt = 0; kt < 2; kt++) {
            uint32_t af[2][4], bf[4][2];
            #pragma unroll
            for (int i = 0; i < 2; i++) {
                int r0 = (wr1 * 2 + i) * 16 + gid;
                af[i][0] = xs[r0 * XS + kt * 8 + tig];
                af[i][1] = xs[(r0 + 8) * XS + kt * 8 + tig];
                af[i][2] = xs[r0 * XS + kt * 8 + tig + 4];
                af[i][3] = xs[(r0 + 8) * XS + kt * 8 + tig + 4];
            }
            #pragma unroll
            for (int j = 0; j < 4; j++) {
                int nc = (wc1 * 4 + j) * 8 + gid;
                bf[j][0] = rs[(kt * 8 + tig) * DP + nc];
                bf[j][1] = rs[(kt * 8 + tig + 4) * DP + nc];
            }
            #pragma unroll
            for (int i = 0; i < 2; i++)
                #pragma unroll
                for (int j = 0; j < 4; j++)
                    mma8(accT[i][j], af[i], bf[j]);
        }
    }

    // ---- store T (tf32) ----
    #pragma unroll
    for (int i = 0; i < 2; i++)
        #pragma unroll
        for (int j = 0; j < 4; j++) {
            int r0 = (wr1 * 2 + i) * 16 + gid;
            int nc = (wc1 * 4 + j) * 8 + 2 * tig;
            uint2 lo = make_uint2(f2tf(accT[i][j][0]), f2tf(accT[i][j][1]));
            uint2 hi = make_uint2(f2tf(accT[i][j][2]), f2tf(accT[i][j][3]));
            *(uint2*)&ts[r0 * DP + nc]       = lo;
            *(uint2*)&ts[(r0 + 8) * DP + nc] = hi;
        }
    __syncthreads();   // T visible; x chunk (lts alias) free to overwrite

    // ================= GEMM2 =================
    const int m   = w >> 2;           // 4 warps per m-row
    const int sw  = w & 3;
    const int wr2 = sw / GC2, wc2 = sw % GC2;
    float accY[2][4][4];
    #pragma unroll
    for (int i = 0; i < 2; i++)
        #pragma unroll
        for (int j = 0; j < 4; j++)
            #pragma unroll
            for (int q = 0; q < 4; q++) accY[i][j][q] = 0.0f;

    for (int ac = 0; ac < NC2; ac++) {
        if (ac) __syncthreads();   // protect lts overwrite vs previous mma reads
        // ---- LT chunk: [B][32 a], L transposed, /3, tf32, stride LTS ----
        #pragma unroll
        for (int i = tid; i < 32 * B; i += THREADS) {
            int acx = i / B, b = i % B;
            lts[b * LTS + acx] = f2tf(Lg[(ac * 32 + acx) * B + b] * (1.0f / 3.0f));
        }
        __syncthreads();

        #pragma unroll
        for (int kt = 0; kt < 4; kt++) {
            uint32_t af[2][4], bf[4][2];
            #pragma unroll
            for (int i = 0; i < 2; i++) {
                int rb = (wr2 * 2 + i) * 16 + gid;
                af[i][0] = lts[rb * LTS + kt * 8 + tig];
                af[i][1] = lts[(rb + 8) * LTS + kt * 8 + tig];
                af[i][2] = lts[rb * LTS + kt * 8 + tig + 4];
                af[i][3] = lts[(rb + 8) * LTS + kt * 8 + tig + 4];
            }
            #pragma unroll
            for (int j = 0; j < 4; j++) {
                int nc = (wc2 * 4 + j) * 8 + gid;
                bf[j][0] = ts[(m * A + ac * 32 + kt * 8 + tig) * DP + nc];
                bf[j][1] = ts[(m * A + ac * 32 + kt * 8 + tig + 4) * DP + nc];
            }
            #pragma unroll
            for (int i = 0; i < 2; i++)
                #pragma unroll
                for (int j = 0; j < 4; j++)
                    mma8(accY[i][j], af[i], bf[j]);
        }
    }

    // ---- RMW y (swizzled): ownership disjoint per thread within a factor ----
    #pragma unroll
    for (int i = 0; i < 2; i++)
        #pragma unroll
        for (int j = 0; j < 4; j++) {
            int b = (wr2 * 2 + i) * 16 + gid;
            int d = (wc2 * 4 + j) * 8 + 2 * tig;
            int n0 = b * D + d;
            int s0 = n0 + 2 * (n0 >> 5);
            float2 v0 = *(float2*)&ys[m * YS + s0];
            v0.x += accY[i][j][0]; v0.y += accY[i][j][1];
            *(float2*)&ys[m * YS + s0] = v0;
            int n2 = (b + 8) * D + d;
            int s2 = n2 + 2 * (n2 >> 5);
            float2 v2 = *(float2*)&ys[m * YS + s2];
            v2.x += accY[i][j][2]; v2.y += accY[i][j][3];
            *(float2*)&ys[m * YS + s2] = v2;
        }
}

__global__ __launch_bounds__(THREADS, 2) void klinear_kernel(
    const float* __restrict__ x,
    const float* __restrict__ L0, const float* __restrict__ R0,
    const float* __restrict__ L1, const float* __restrict__ R1,
    const float* __restrict__ L2, const float* __restrict__ R2,
    const float* __restrict__ bias,
    float* __restrict__ out)
{
    extern __shared__ float smem[];
    const int tid = threadIdx.x;
    const int m0  = blockIdx.x * MT;

    // zero y accumulator (bias added in epilogue)
    for (int i = tid; i < MT * YS; i += THREADS)
        smem[OFF_Y + i] = 0.0f;
    // (first factor's chunk-top __syncthreads orders this before any use)

    factor< 64,  64,  64,  64>(x, L0, R0, smem, m0, tid);
    factor< 32,  32, 128, 128>(x, L1, R1, smem, m0, tid);
    factor<128, 128,  32,  32>(x, L2, R2, smem, m0, tid);

    __syncthreads();

    // epilogue: y + bias -> out; thread owns n in [16*tid, 16*tid+16)
    const int n0 = tid * 16;
    #pragma unroll
    for (int h = 0; h < 2; h++) {
        int nb = n0 + h * 8;
        int s  = nb + 2 * (nb >> 5);   // constant shift within each 8-run
        float4 b0 = *(const float4*)&bias[nb];
        float4 b1 = *(const float4*)&bias[nb + 4];
        #pragma unroll
        for (int m = 0; m < MT; m++) {
            const float* yr = smem + OFF_Y + m * YS + s;
            float2 p0 = *(const float2*)&yr[0];
            float2 p1 = *(const float2*)&yr[2];
            float2 p2 = *(const float2*)&yr[4];
            float2 p3 = *(const float2*)&yr[6];
            float4 o0 = make_float4(p0.x + b0.x, p0.y + b0.y, p1.x + b0.z, p1.y + b0.w);
            float4 o1 = make_float4(p2.x + b1.x, p2.y + b1.y, p3.x + b1.z, p3.y + b1.w);
            *(float4*)&out[(size_t)(m0 + m) * NF + nb]     = o0;
            *(float4*)&out[(size_t)(m0 + m) * NF + nb + 4] = o1;
        }
    }
}

extern "C" void kernel_launch(void* const* d_in, const int* in_sizes, int n_in,
                              void* d_out, int out_size)
{
    const float* x    = (const float*)d_in[0];
    const float* L0   = (const float*)d_in[1];
    const float* R0   = (const float*)d_in[2];
    const float* L1   = (const float*)d_in[3];
    const float* R1   = (const float*)d_in[4];
    const float* L2   = (const float*)d_in[5];
    const float* R2   = (const float*)d_in[6];
    const float* bias = (const float*)d_in[7];
    float* out = (float*)d_out;

    static bool attr_set = false;
    if (!attr_set) {
        cudaFuncSetAttribute(klinear_kernel,
                             cudaFuncAttributeMaxDynamicSharedMemorySize, SMEM_BYTES);
        attr_set = true;
    }

    klinear_kernel<<<16384 / MT, THREADS, SMEM_BYTES>>>(
        x, L0, R0, L1, R1, L2, R2, bias, out);
}

// round 14
// speedup vs baseline: 1.0848x; 1.0241x over previous
#include <cuda_runtime.h>
#include <cstdint>

// ============================================================================
// KLinear: y = x @ W + bias,  W = (kron(L0,R0)+kron(L1,R1)+kron(L2,R2))/3
// Factorized two-stage GEMMs on mma.sync m16n8k8 tf32 (base ISA).
//   GEMM1: T[(m,a), d] = sum_c x[m, a*C+c] * R[c,d]
//   GEMM2: y[m][b*D+d] += sum_a (L[a,b]/3) * T[(m,a), d]
// R14 = R11 (proven, 801us) + register-staged prefetch in GEMM1: chunk ck+1's
// LDGs issue right after chunk ck's STS, overlapping the mma consume phase.
// Same smem layout, same consume code, same numerics as R11.
// ============================================================================

static constexpr int THREADS = 256;
static constexpr int MT = 2;
static constexpr int NF = 4096;

// SMEM layout (float indices) — identical to R11
static constexpr int YS    = 4352;     // 4096 + 2*(4096/32)
static constexpr int OFF_Y = 0;        // 2*4352 = 8704
static constexpr int OFF_T = 8704;     // max MT*A*DP = 256*40 = 10240
static constexpr int OFF_X = 18944;    // x chunk / LT staging (aliased)
static constexpr int OFF_R = 24064;    // 16*136 max = 2176
static constexpr int SMEM_FLOATS = 26240;
static constexpr int SMEM_BYTES  = SMEM_FLOATS * 4;   // 104960

__device__ __forceinline__ uint32_t f2tf(float f) {
    uint32_t r; asm("cvt.rna.tf32.f32 %0, %1;" : "=r"(r) : "f"(f)); return r;
}

__device__ __forceinline__ void mma8(float* c, const uint32_t* a, const uint32_t* b) {
    asm volatile(
        "mma.sync.aligned.m16n8k8.row.col.f32.tf32.tf32.f32 "
        "{%0,%1,%2,%3}, {%4,%5,%6,%7}, {%8,%9}, {%0,%1,%2,%3};"
        : "+f"(c[0]), "+f"(c[1]), "+f"(c[2]), "+f"(c[3])
        : "r"(a[0]), "r"(a[1]), "r"(a[2]), "r"(a[3]), "r"(b[0]), "r"(b[1]));
}

template<int A, int B, int C, int D>
__device__ __forceinline__ void factor(
    const float* __restrict__ x, const float* __restrict__ Lg,
    const float* __restrict__ Rg, float* __restrict__ smem, int m0, int tid)
{
    constexpr int DP  = D + 8;      // padded row stride (R, T)
    constexpr int XS  = 20;         // x chunk row stride (16 + 4)
    constexpr int LTS = 36;         // LT chunk row stride (32 + 4)
    constexpr int NC1 = C / 16;     // K chunks, stage 1
    constexpr int NC2 = A / 32;     // K chunks, stage 2
    constexpr int GC1 = D / 32;     // GEMM1 warp-grid cols (2x4-tile blocks)
    constexpr int GC2 = D / 32;     // GEMM2 warp-grid cols
    constexpr int XN  = (MT * A * 4) / THREADS;            // 2 / 1 / 4 (exact)
    constexpr int RN  = (4 * D + THREADS - 1) / THREADS;   // 1 / 2 / 1
    constexpr bool RGUARD = (4 * D % THREADS) != 0;        // true only for D=32

    float*    ys  = smem + OFF_Y;
    uint32_t* ts  = (uint32_t*)(smem + OFF_T);
    uint32_t* xs  = (uint32_t*)(smem + OFF_X);
    uint32_t* rs  = (uint32_t*)(smem + OFF_R);
    uint32_t* lts = (uint32_t*)(smem + OFF_X);   // alias (x chunk dead in GEMM2)

    const int w    = tid >> 5;
    const int lane = tid & 31;
    const int gid  = lane >> 2;
    const int tig  = lane & 3;

    // ---- register-staged chunk prefetch ----
    float4 xpf[XN];
    float4 rpf[RN];
    auto ldg_chunk = [&](int ck) {
        #pragma unroll
        for (int u = 0; u < XN; u++) {
            int s = tid + u * THREADS;
            int r = s >> 2, c4 = s & 3;
            int m = r / A, a = r % A;
            xpf[u] = *(const float4*)&x[(size_t)(m0 + m) * NF + a * C + ck * 16 + c4 * 4];
        }
        #pragma unroll
        for (int u = 0; u < RN; u++) {
            int s = tid + u * THREADS;
            if (!RGUARD || s < 4 * D) {
                int k = s / (D / 4), d4 = s % (D / 4);
                rpf[u] = *(const float4*)&Rg[(ck * 16 + k) * D + d4 * 4];
            }
        }
    };
    auto sts_chunk = [&]() {
        #pragma unroll
        for (int u = 0; u < XN; u++) {
            int s = tid + u * THREADS;
            int r = s >> 2, c4 = s & 3;
            uint4 q = make_uint4(f2tf(xpf[u].x), f2tf(xpf[u].y),
                                 f2tf(xpf[u].z), f2tf(xpf[u].w));
            *(uint4*)&xs[r * XS + c4 * 4] = q;
        }
        #pragma unroll
        for (int u = 0; u < RN; u++) {
            int s = tid + u * THREADS;
            if (!RGUARD || s < 4 * D) {
                int k = s / (D / 4), d4 = s % (D / 4);
                uint4 q = make_uint4(f2tf(rpf[u].x), f2tf(rpf[u].y),
                                     f2tf(rpf[u].z), f2tf(rpf[u].w));
                *(uint4*)&rs[k * DP + d4 * 4] = q;
            }
        }
    };

    // ================= GEMM1 =================
    const int wr1 = w / GC1, wc1 = w % GC1;
    float accT[2][4][4];
    #pragma unroll
    for (int i = 0; i < 2; i++)
        #pragma unroll
        for (int j = 0; j < 4; j++)
            #pragma unroll
            for (int q = 0; q < 4; q++) accT[i][j][q] = 0.0f;

    ldg_chunk(0);   // global reads only — safe before the barrier
    for (int ck = 0; ck < NC1; ck++) {
        __syncthreads();           // buffers free (prev consume / prev factor done)
        sts_chunk();               // store chunk ck
        if (ck + 1 < NC1) ldg_chunk(ck + 1);   // prefetch: in flight during consume
        __syncthreads();           // chunk ck visible

        #pragma unroll
        for (int kt = 0; kt < 2; kt++) {
            uint32_t af[2][4], bf[4][2];
            #pragma unroll
            for (int i = 0; i < 2; i++) {
                int r0 = (wr1 * 2 + i) * 16 + gid;
                af[i][0] = xs[r0 * XS + kt * 8 + tig];
                af[i][1] = xs[(r0 + 8) * XS + kt * 8 + tig];
                af[i][2] = xs[r0 * XS + kt * 8 + tig + 4];
                af[i][3] = xs[(r0 + 8) * XS + kt * 8 + tig + 4];
            }
            #pragma unroll
            for (int j = 0; j < 4; j++) {
                int nc = (wc1 * 4 + j) * 8 + gid;
                bf[j][0] = rs[(kt * 8 + tig) * DP + nc];
                bf[j][1] = rs[(kt * 8 + tig + 4) * DP + nc];
            }
            #pragma unroll
            for (int i = 0; i < 2; i++)
                #pragma unroll
                for (int j = 0; j < 4; j++)
                    mma8(accT[i][j], af[i], bf[j]);
        }
    }

    // ---- store T (tf32): rows (m,a), cols d ----
    __syncthreads();   // all consumes done before T overwrites nothing; keeps order vs next writes
    #pragma unroll
    for (int i = 0; i < 2; i++)
        #pragma unroll
        for (int j = 0; j < 4; j++) {
            int r0 = (wr1 * 2 + i) * 16 + gid;
            int nc = (wc1 * 4 + j) * 8 + 2 * tig;
            uint2 lo = make_uint2(f2tf(accT[i][j][0]), f2tf(accT[i][j][1]));
            uint2 hi = make_uint2(f2tf(accT[i][j][2]), f2tf(accT[i][j][3]));
            *(uint2*)&ts[r0 * DP + nc]       = lo;
            *(uint2*)&ts[(r0 + 8) * DP + nc] = hi;
        }
    __syncthreads();   // T visible; x chunk (lts alias) free to overwrite

    // ================= GEMM2 (R11 proven form) =================
    const int m   = w >> 2;           // 4 warps per m-row
    const int sw  = w & 3;
    const int wr2 = sw / GC2, wc2 = sw % GC2;
    float accY[2][4][4];
    #pragma unroll
    for (int i = 0; i < 2; i++)
        #pragma unroll
        for (int j = 0; j < 4; j++)
            #pragma unroll
            for (int q = 0; q < 4; q++) accY[i][j][q] = 0.0f;

    for (int ac = 0; ac < NC2; ac++) {
        if (ac) __syncthreads();   // protect lts overwrite vs previous mma reads
        // ---- LT chunk: [B][32 a], L transposed, /3, tf32, stride LTS ----
        #pragma unroll
        for (int i = tid; i < 32 * B; i += THREADS) {
            int acx = i / B, b = i % B;
            lts[b * LTS + acx] = f2tf(Lg[(ac * 32 + acx) * B + b] * (1.0f / 3.0f));
        }
        __syncthreads();

        #pragma unroll
        for (int kt = 0; kt < 4; kt++) {
            uint32_t af[2][4], bf[4][2];
            #pragma unroll
            for (int i = 0; i < 2; i++) {
                int rb = (wr2 * 2 + i) * 16 + gid;
                af[i][0] = lts[rb * LTS + kt * 8 + tig];
                af[i][1] = lts[(rb + 8) * LTS + kt * 8 + tig];
                af[i][2] = lts[rb * LTS + kt * 8 + tig + 4];
                af[i][3] = lts[(rb + 8) * LTS + kt * 8 + tig + 4];
            }
            #pragma unroll
            for (int j = 0; j < 4; j++) {
                int nc = (wc2 * 4 + j) * 8 + gid;
                bf[j][0] = ts[(m * A + ac * 32 + kt * 8 + tig) * DP + nc];
                bf[j][1] = ts[(m * A + ac * 32 + kt * 8 + tig + 4) * DP + nc];
            }
            #pragma unroll
            for (int i = 0; i < 2; i++)
                #pragma unroll
                for (int j = 0; j < 4; j++)
                    mma8(accY[i][j], af[i], bf[j]);
        }
    }

    // ---- RMW y (swizzled): per-thread disjoint within a factor ----
    #pragma unroll
    for (int i = 0; i < 2; i++)
        #pragma unroll
        for (int j = 0; j < 4; j++) {
            int b = (wr2 * 2 + i) * 16 + gid;
            int d = (wc2 * 4 + j) * 8 + 2 * tig;
            int n0 = b * D + d;
            int s0 = n0 + 2 * (n0 >> 5);
            float2 v0 = *(float2*)&ys[m * YS + s0];
            v0.x += accY[i][j][0]; v0.y += accY[i][j][1];
            *(float2*)&ys[m * YS + s0] = v0;
            int n2 = (b + 8) * D + d;
            int s2 = n2 + 2 * (n2 >> 5);
            float2 v2 = *(float2*)&ys[m * YS + s2];
            v2.x += accY[i][j][2]; v2.y += accY[i][j][3];
            *(float2*)&ys[m * YS + s2] = v2;
        }
}

__global__ __launch_bounds__(THREADS, 2) void klinear_kernel(
    const float* __restrict__ x,
    const float* __restrict__ L0, const float* __restrict__ R0,
    const float* __restrict__ L1, const float* __restrict__ R1,
    const float* __restrict__ L2, const float* __restrict__ R2,
    const float* __restrict__ bias,
    float* __restrict__ out)
{
    extern __shared__ float smem[];
    const int tid = threadIdx.x;
    const int m0  = blockIdx.x * MT;

    // zero y accumulator (bias added in epilogue)
    for (int i = tid; i < MT * YS; i += THREADS)
        smem[OFF_Y + i] = 0.0f;
    // (first factor's chunk-top __syncthreads orders this before any use)

    factor< 64,  64,  64,  64>(x, L0, R0, smem, m0, tid);
    factor< 32,  32, 128, 128>(x, L1, R1, smem, m0, tid);
    factor<128, 128,  32,  32>(x, L2, R2, smem, m0, tid);

    __syncthreads();

    // epilogue: y + bias -> out; thread owns n in [16*tid, 16*tid+16)
    const int n0 = tid * 16;
    #pragma unroll
    for (int h = 0; h < 2; h++) {
        int nb = n0 + h * 8;
        int s  = nb + 2 * (nb >> 5);   // constant shift within each 8-run
        float4 b0 = *(const float4*)&bias[nb];
        float4 b1 = *(const float4*)&bias[nb + 4];
        #pragma unroll
        for (int m = 0; m < MT; m++) {
            const float* yr = smem + OFF_Y + m * YS + s;
            float2 p0 = *(const float2*)&yr[0];
            float2 p1 = *(const float2*)&yr[2];
            float2 p2 = *(const float2*)&yr[4];
            float2 p3 = *(const float2*)&yr[6];
            float4 o0 = make_float4(p0.x + b0.x, p0.y + b0.y, p1.x + b0.z, p1.y + b0.w);
            float4 o1 = make_float4(p2.x + b1.x, p2.y + b1.y, p3.x + b1.z, p3.y + b1.w);
            *(float4*)&out[(size_t)(m0 + m) * NF + nb]     = o0;
            *(float4*)&out[(size_t)(m0 + m) * NF + nb + 4] = o1;
        }
    }
}

extern "C" void kernel_launch(void* const* d_in, const int* in_sizes, int n_in,
                              void* d_out, int out_size)
{
    const float* x    = (const float*)d_in[0];
    const float* L0   = (const float*)d_in[1];
    const float* R0   = (const float*)d_in[2];
    const float* L1   = (const float*)d_in[3];
    const float* R1   = (const float*)d_in[4];
    const float* L2   = (const float*)d_in[5];
    const float* R2   = (const float*)d_in[6];
    const float* bias = (const float*)d_in[7];
    float* out = (float*)d_out;

    static bool attr_set = false;
    if (!attr_set) {
        cudaFuncSetAttribute(klinear_kernel,
                             cudaFuncAttributeMaxDynamicSharedMemorySize, SMEM_BYTES);
        attr_set = true;
    }

    klinear_kernel<<<16384 / MT, THREADS, SMEM_BYTES>>>(
        x, L0, R0, L1, R1, L2, R2, bias, out);
}

// round 15
// speedup vs baseline: 1.0858x; 1.0009x over previous
#include <cuda_runtime.h>
#include <cstdint>

// ============================================================================
// KLinear: y = x @ W + bias,  W = (kron(L0,R0)+kron(L1,R1)+kron(L2,R2))/3
// Factorized two-stage GEMMs on mma.sync m16n8k8 tf32 (base ISA).
//   GEMM1: T[(m,a), d] = sum_c x[m, a*C+c] * R[c,d]
//   GEMM2: y[m][b*D+d] += sum_a (L[a,b]/3) * T[(m,a), d]
// R14 = R11 (proven, 801us) + register-staged prefetch in GEMM1: chunk ck+1's
// LDGs issue right after chunk ck's STS, overlapping the mma consume phase.
// Same smem layout, same consume code, same numerics as R11.
// ============================================================================

static constexpr int THREADS = 256;
static constexpr int MT = 2;
static constexpr int NF = 4096;

// SMEM layout (float indices) — identical to R11
static constexpr int YS    = 4352;     // 4096 + 2*(4096/32)
static constexpr int OFF_Y = 0;        // 2*4352 = 8704
static constexpr int OFF_T = 8704;     // max MT*A*DP = 256*40 = 10240
static constexpr int OFF_X = 18944;    // x chunk / LT staging (aliased)
static constexpr int OFF_R = 24064;    // 16*136 max = 2176
static constexpr int SMEM_FLOATS = 26240;
static constexpr int SMEM_BYTES  = SMEM_FLOATS * 4;   // 104960

__device__ __forceinline__ uint32_t f2tf(float f) {
    uint32_t r; asm("cvt.rna.tf32.f32 %0, %1;" : "=r"(r) : "f"(f)); return r;
}

__device__ __forceinline__ void mma8(float* c, const uint32_t* a, const uint32_t* b) {
    asm volatile(
        "mma.sync.aligned.m16n8k8.row.col.f32.tf32.tf32.f32 "
        "{%0,%1,%2,%3}, {%4,%5,%6,%7}, {%8,%9}, {%0,%1,%2,%3};"
        : "+f"(c[0]), "+f"(c[1]), "+f"(c[2]), "+f"(c[3])
        : "r"(a[0]), "r"(a[1]), "r"(a[2]), "r"(a[3]), "r"(b[0]), "r"(b[1]));
}

template<int A, int B, int C, int D>
__device__ __forceinline__ void factor(
    const float* __restrict__ x, const float* __restrict__ Lg,
    const float* __restrict__ Rg, float* __restrict__ smem, int m0, int tid)
{
    constexpr int DP  = D + 8;      // padded row stride (R, T)
    constexpr int XS  = 20;         // x chunk row stride (16 + 4)
    constexpr int LTS = 36;         // LT chunk row stride (32 + 4)
    constexpr int NC1 = C / 16;     // K chunks, stage 1
    constexpr int NC2 = A / 32;     // K chunks, stage 2
    constexpr int GC1 = D / 32;     // GEMM1 warp-grid cols (2x4-tile blocks)
    constexpr int GC2 = D / 32;     // GEMM2 warp-grid cols
    constexpr int XN  = (MT * A * 4) / THREADS;            // 2 / 1 / 4 (exact)
    constexpr int RN  = (4 * D + THREADS - 1) / THREADS;   // 1 / 2 / 1
    constexpr bool RGUARD = (4 * D % THREADS) != 0;        // true only for D=32

    float*    ys  = smem + OFF_Y;
    uint32_t* ts  = (uint32_t*)(smem + OFF_T);
    uint32_t* xs  = (uint32_t*)(smem + OFF_X);
    uint32_t* rs  = (uint32_t*)(smem + OFF_R);
    uint32_t* lts = (uint32_t*)(smem + OFF_X);   // alias (x chunk dead in GEMM2)

    const int w    = tid >> 5;
    const int lane = tid & 31;
    const int gid  = lane >> 2;
    const int tig  = lane & 3;

    // ---- register-staged chunk prefetch ----
    float4 xpf[XN];
    float4 rpf[RN];
    auto ldg_chunk = [&](int ck) {
        #pragma unroll
        for (int u = 0; u < XN; u++) {
            int s = tid + u * THREADS;
            int r = s >> 2, c4 = s & 3;
            int m = r / A, a = r % A;
            xpf[u] = *(const float4*)&x[(size_t)(m0 + m) * NF + a * C + ck * 16 + c4 * 4];
        }
        #pragma unroll
        for (int u = 0; u < RN; u++) {
            int s = tid + u * THREADS;
            if (!RGUARD || s < 4 * D) {
                int k = s / (D / 4), d4 = s % (D / 4);
                rpf[u] = *(const float4*)&Rg[(ck * 16 + k) * D + d4 * 4];
            }
        }
    };
    auto sts_chunk = [&]() {
        #pragma unroll
        for (int u = 0; u < XN; u++) {
            int s = tid + u * THREADS;
            int r = s >> 2, c4 = s & 3;
            uint4 q = make_uint4(f2tf(xpf[u].x), f2tf(xpf[u].y),
                                 f2tf(xpf[u].z), f2tf(xpf[u].w));
            *(uint4*)&xs[r * XS + c4 * 4] = q;
        }
        #pragma unroll
        for (int u = 0; u < RN; u++) {
            int s = tid + u * THREADS;
            if (!RGUARD || s < 4 * D) {
                int k = s / (D / 4), d4 = s % (D / 4);
                uint4 q = make_uint4(f2tf(rpf[u].x), f2tf(rpf[u].y),
                                     f2tf(rpf[u].z), f2tf(rpf[u].w));
                *(uint4*)&rs[k * DP + d4 * 4] = q;
            }
        }
    };

    // ================= GEMM1 =================
    const int wr1 = w / GC1, wc1 = w % GC1;
    float accT[2][4][4];
    #pragma unroll
    for (int i = 0; i < 2; i++)
        #pragma unroll
        for (int j = 0; j < 4; j++)
            #pragma unroll
            for (int q = 0; q < 4; q++) accT[i][j][q] = 0.0f;

    ldg_chunk(0);   // global reads only — safe before the barrier
    for (int ck = 0; ck < NC1; ck++) {
        __syncthreads();           // buffers free (prev consume / prev factor done)
        sts_chunk();               // store chunk ck
        if (ck + 1 < NC1) ldg_chunk(ck + 1);   // prefetch: in flight during consume
        __syncthreads();           // chunk ck visible

        #pragma unroll
        for (int kt = 0; kt < 2; kt++) {
            uint32_t af[2][4], bf[4][2];
            #pragma unroll
            for (int i = 0; i < 2; i++) {
                int r0 = (wr1 * 2 + i) * 16 + gid;
                af[i][0] = xs[r0 * XS + kt * 8 + tig];
                af[i][1] = xs[(r0 + 8) * XS + kt * 8 + tig];
                af[i][2] = xs[r0 * XS + kt * 8 + tig + 4];
                af[i][3] = xs[(r0 + 8) * XS + kt * 8 + tig + 4];
            }
            #pragma unroll
            for (int j = 0; j < 4; j++) {
                int nc = (wc1 * 4 + j) * 8 + gid;
                bf[j][0] = rs[(kt * 8 + tig) * DP + nc];
                bf[j][1] = rs[(kt * 8 + tig + 4) * DP + nc];
            }
            #pragma unroll
            for (int i = 0; i < 2; i++)
                #pragma unroll
                for (int j = 0; j < 4; j++)
                    mma8(accT[i][j], af[i], bf[j]);
        }
    }

    // ---- store T (tf32): rows (m,a), cols d ----
    __syncthreads();   // all consumes done before T overwrites nothing; keeps order vs next writes
    #pragma unroll
    for (int i = 0; i < 2; i++)
        #pragma unroll
        for (int j = 0; j < 4; j++) {
            int r0 = (wr1 * 2 + i) * 16 + gid;
            int nc = (wc1 * 4 + j) * 8 + 2 * tig;
            uint2 lo = make_uint2(f2tf(accT[i][j][0]), f2tf(accT[i][j][1]));
            uint2 hi = make_uint2(f2tf(accT[i][j][2]), f2tf(accT[i][j][3]));
            *(uint2*)&ts[r0 * DP + nc]       = lo;
            *(uint2*)&ts[(r0 + 8) * DP + nc] = hi;
        }
    __syncthreads();   // T visible; x chunk (lts alias) free to overwrite

    // ================= GEMM2 (R11 proven form) =================
    const int m   = w >> 2;           // 4 warps per m-row
    const int sw  = w & 3;
    const int wr2 = sw / GC2, wc2 = sw % GC2;
    float accY[2][4][4];
    #pragma unroll
    for (int i = 0; i < 2; i++)
        #pragma unroll
        for (int j = 0; j < 4; j++)
            #pragma unroll
            for (int q = 0; q < 4; q++) accY[i][j][q] = 0.0f;

    for (int ac = 0; ac < NC2; ac++) {
        if (ac) __syncthreads();   // protect lts overwrite vs previous mma reads
        // ---- LT chunk: [B][32 a], L transposed, /3, tf32, stride LTS ----
        #pragma unroll
        for (int i = tid; i < 32 * B; i += THREADS) {
            int acx = i / B, b = i % B;
            lts[b * LTS + acx] = f2tf(Lg[(ac * 32 + acx) * B + b] * (1.0f / 3.0f));
        }
        __syncthreads();

        #pragma unroll
        for (int kt = 0; kt < 4; kt++) {
            uint32_t af[2][4], bf[4][2];
            #pragma unroll
            for (int i = 0; i < 2; i++) {
                int rb = (wr2 * 2 + i) * 16 + gid;
                af[i][0] = lts[rb * LTS + kt * 8 + tig];
                af[i][1] = lts[(rb + 8) * LTS + kt * 8 + tig];
                af[i][2] = lts[rb * LTS + kt * 8 + tig + 4];
                af[i][3] = lts[(rb + 8) * LTS + kt * 8 + tig + 4];
            }
            #pragma unroll
            for (int j = 0; j < 4; j++) {
                int nc = (wc2 * 4 + j) * 8 + gid;
                bf[j][0] = ts[(m * A + ac * 32 + kt * 8 + tig) * DP + nc];
                bf[j][1] = ts[(m * A + ac * 32 + kt * 8 + tig + 4) * DP + nc];
            }
            #pragma unroll
            for (int i = 0; i < 2; i++)
                #pragma unroll
                for (int j = 0; j < 4; j++)
                    mma8(accY[i][j], af[i], bf[j]);
        }
    }

    // ---- RMW y (swizzled): per-thread disjoint within a factor ----
    #pragma unroll
    for (int i = 0; i < 2; i++)
        #pragma unroll
        for (int j = 0; j < 4; j++) {
            int b = (wr2 * 2 + i) * 16 + gid;
            int d = (wc2 * 4 + j) * 8 + 2 * tig;
            int n0 = b * D + d;
            int s0 = n0 + 2 * (n0 >> 5);
            float2 v0 = *(float2*)&ys[m * YS + s0];
            v0.x += accY[i][j][0]; v0.y += accY[i][j][1];
            *(float2*)&ys[m * YS + s0] = v0;
            int n2 = (b + 8) * D + d;
            int s2 = n2 + 2 * (n2 >> 5);
            float2 v2 = *(float2*)&ys[m * YS + s2];
            v2.x += accY[i][j][2]; v2.y += accY[i][j][3];
            *(float2*)&ys[m * YS + s2] = v2;
        }
}

__global__ __launch_bounds__(THREADS, 2) void klinear_kernel(
    const float* __restrict__ x,
    const float* __restrict__ L0, const float* __restrict__ R0,
    const float* __restrict__ L1, const float* __restrict__ R1,
    const float* __restrict__ L2, const float* __restrict__ R2,
    const float* __restrict__ bias,
    float* __restrict__ out)
{
    extern __shared__ float smem[];
    const int tid = threadIdx.x;
    const int m0  = blockIdx.x * MT;

    // zero y accumulator (bias added in epilogue)
    for (int i = tid; i < MT * YS; i += THREADS)
        smem[OFF_Y + i] = 0.0f;
    // (first factor's chunk-top __syncthreads orders this before any use)

    factor< 64,  64,  64,  64>(x, L0, R0, smem, m0, tid);
    factor< 32,  32, 128, 128>(x, L1, R1, smem, m0, tid);
    factor<128, 128,  32,  32>(x, L2, R2, smem, m0, tid);

    __syncthreads();

    // epilogue: y + bias -> out; thread owns n in [16*tid, 16*tid+16)
    const int n0 = tid * 16;
    #pragma unroll
    for (int h = 0; h < 2; h++) {
        int nb = n0 + h * 8;
        int s  = nb + 2 * (nb >> 5);   // constant shift within each 8-run
        float4 b0 = *(const float4*)&bias[nb];
        float4 b1 = *(const float4*)&bias[nb + 4];
        #pragma unroll
        for (int m = 0; m < MT; m++) {
            const float* yr = smem + OFF_Y + m * YS + s;
            float2 p0 = *(const float2*)&yr[0];
            float2 p1 = *(const float2*)&yr[2];
            float2 p2 = *(const float2*)&yr[4];
            float2 p3 = *(const float2*)&yr[6];
            float4 o0 = make_float4(p0.x + b0.x, p0.y + b0.y, p1.x + b0.z, p1.y + b0.w);
            float4 o1 = make_float4(p2.x + b1.x, p2.y + b1.y, p3.x + b1.z, p3.y + b1.w);
            *(float4*)&out[(size_t)(m0 + m) * NF + nb]     = o0;
            *(float4*)&out[(size_t)(m0 + m) * NF + nb + 4] = o1;
        }
    }
}

extern "C" void kernel_launch(void* const* d_in, const int* in_sizes, int n_in,
                              void* d_out, int out_size)
{
    const float* x    = (const float*)d_in[0];
    const float* L0   = (const float*)d_in[1];
    const float* R0   = (const float*)d_in[2];
    const float* L1   = (const float*)d_in[3];
    const float* R1   = (const float*)d_in[4];
    const float* L2   = (const float*)d_in[5];
    const float* R2   = (const float*)d_in[6];
    const float* bias = (const float*)d_in[7];
    float* out = (float*)d_out;

    static bool attr_set = false;
    if (!attr_set) {
        cudaFuncSetAttribute(klinear_kernel,
                             cudaFuncAttributeMaxDynamicSharedMemorySize, SMEM_BYTES);
        attr_set = true;
    }

    klinear_kernel<<<16384 / MT, THREADS, SMEM_BYTES>>>(
        x, L0, R0, L1, R1, L2, R2, bias, out);
}

// round 16
// speedup vs baseline: 1.1970x; 1.1025x over previous
#include <cuda_runtime.h>
#include <cstdint>

// ============================================================================
// KLinear: y = x @ W + bias,  W = (kron(L0,R0)+kron(L1,R1)+kron(L2,R2))/3
// Factorized two-stage GEMMs on mma.sync m16n8k8 tf32 (base ISA).
//   GEMM1: T[(m,a), d] = sum_c x[m, a*C+c] * R[c,d]
//   GEMM2: y[m][b*D+d] += sum_a (L[a,b]/3) * T[(m,a), d]
// R16 = R15 + GEMM2 L staging in NATIVE [a][b] layout (float4, conflict-free);
// A-fragments of L^T read directly from it (banks 8*tig+gid, conflict-free).
// Replaces the 4-way-conflicted transposed staging. Values identical to R15.
// ============================================================================

static constexpr int THREADS = 256;
static constexpr int MT = 2;
static constexpr int NF = 4096;

// SMEM layout (float indices)
static constexpr int YS    = 4352;     // 4096 + 2*(4096/32)
static constexpr int OFF_Y = 0;        // 2*4352 = 8704
static constexpr int OFF_T = 8704;     // max MT*A*DP = 256*40 = 10240
static constexpr int OFF_X = 18944;    // x chunk / L staging (aliased), 5120
static constexpr int OFF_R = 24064;    // 16*136 max = 2176
static constexpr int SMEM_FLOATS = 26240;
static constexpr int SMEM_BYTES  = SMEM_FLOATS * 4;   // 104960

__device__ __forceinline__ uint32_t f2tf(float f) {
    uint32_t r; asm("cvt.rna.tf32.f32 %0, %1;" : "=r"(r) : "f"(f)); return r;
}

__device__ __forceinline__ void mma8(float* c, const uint32_t* a, const uint32_t* b) {
    asm volatile(
        "mma.sync.aligned.m16n8k8.row.col.f32.tf32.tf32.f32 "
        "{%0,%1,%2,%3}, {%4,%5,%6,%7}, {%8,%9}, {%0,%1,%2,%3};"
        : "+f"(c[0]), "+f"(c[1]), "+f"(c[2]), "+f"(c[3])
        : "r"(a[0]), "r"(a[1]), "r"(a[2]), "r"(a[3]), "r"(b[0]), "r"(b[1]));
}

template<int A, int B, int C, int D>
__device__ __forceinline__ void factor(
    const float* __restrict__ x, const float* __restrict__ Lg,
    const float* __restrict__ Rg, float* __restrict__ smem, int m0, int tid)
{
    constexpr int DP  = D + 8;      // padded row stride (R, T)
    constexpr int XS  = 20;         // x chunk row stride (16 + 4)
    constexpr int BS  = B + 8;      // native L row stride (BS % 32 == 8)
    constexpr int NC1 = C / 16;     // K chunks, stage 1
    constexpr int NC2 = A / 32;     // K chunks, stage 2
    constexpr int GC1 = D / 32;     // GEMM1 warp-grid cols (2x4-tile blocks)
    constexpr int GC2 = D / 32;     // GEMM2 warp-grid cols
    constexpr int XN  = (MT * A * 4) / THREADS;            // 2 / 1 / 4 (exact)
    constexpr int RN  = (4 * D + THREADS - 1) / THREADS;   // 1 / 2 / 1
    constexpr bool RGUARD = (4 * D % THREADS) != 0;        // true only for D=32
    constexpr int LN  = (8 * B + THREADS - 1) / THREADS;   // L float4 loads/thread
    constexpr bool LGUARD = (8 * B % THREADS) != 0;        // true only for B=32

    float*    ys   = smem + OFF_Y;
    uint32_t* ts   = (uint32_t*)(smem + OFF_T);
    uint32_t* xs   = (uint32_t*)(smem + OFF_X);
    uint32_t* rs   = (uint32_t*)(smem + OFF_R);
    uint32_t* lnat = (uint32_t*)(smem + OFF_X);   // alias (x chunk dead in GEMM2)

    const int w    = tid >> 5;
    const int lane = tid & 31;
    const int gid  = lane >> 2;
    const int tig  = lane & 3;

    // ---- register-staged chunk prefetch (GEMM1) ----
    float4 xpf[XN];
    float4 rpf[RN];
    auto ldg_chunk = [&](int ck) {
        #pragma unroll
        for (int u = 0; u < XN; u++) {
            int s = tid + u * THREADS;
            int r = s >> 2, c4 = s & 3;
            int m = r / A, a = r % A;
            xpf[u] = *(const float4*)&x[(size_t)(m0 + m) * NF + a * C + ck * 16 + c4 * 4];
        }
        #pragma unroll
        for (int u = 0; u < RN; u++) {
            int s = tid + u * THREADS;
            if (!RGUARD || s < 4 * D) {
                int k = s / (D / 4), d4 = s % (D / 4);
                rpf[u] = *(const float4*)&Rg[(ck * 16 + k) * D + d4 * 4];
            }
        }
    };
    auto sts_chunk = [&]() {
        #pragma unroll
        for (int u = 0; u < XN; u++) {
            int s = tid + u * THREADS;
            int r = s >> 2, c4 = s & 3;
            uint4 q = make_uint4(f2tf(xpf[u].x), f2tf(xpf[u].y),
                                 f2tf(xpf[u].z), f2tf(xpf[u].w));
            *(uint4*)&xs[r * XS + c4 * 4] = q;
        }
        #pragma unroll
        for (int u = 0; u < RN; u++) {
            int s = tid + u * THREADS;
            if (!RGUARD || s < 4 * D) {
                int k = s / (D / 4), d4 = s % (D / 4);
                uint4 q = make_uint4(f2tf(rpf[u].x), f2tf(rpf[u].y),
                                     f2tf(rpf[u].z), f2tf(rpf[u].w));
                *(uint4*)&rs[k * DP + d4 * 4] = q;
            }
        }
    };

    // ================= GEMM1 =================
    const int wr1 = w / GC1, wc1 = w % GC1;
    float accT[2][4][4];
    #pragma unroll
    for (int i = 0; i < 2; i++)
        #pragma unroll
        for (int j = 0; j < 4; j++)
            #pragma unroll
            for (int q = 0; q < 4; q++) accT[i][j][q] = 0.0f;

    ldg_chunk(0);   // global reads only — safe before the barrier
    for (int ck = 0; ck < NC1; ck++) {
        __syncthreads();           // buffers free (prev consume / prev factor done)
        sts_chunk();               // store chunk ck
        if (ck + 1 < NC1) ldg_chunk(ck + 1);   // prefetch: in flight during consume
        __syncthreads();           // chunk ck visible

        #pragma unroll
        for (int kt = 0; kt < 2; kt++) {
            uint32_t af[2][4], bf[4][2];
            #pragma unroll
            for (int i = 0; i < 2; i++) {
                int r0 = (wr1 * 2 + i) * 16 + gid;
                af[i][0] = xs[r0 * XS + kt * 8 + tig];
                af[i][1] = xs[(r0 + 8) * XS + kt * 8 + tig];
                af[i][2] = xs[r0 * XS + kt * 8 + tig + 4];
                af[i][3] = xs[(r0 + 8) * XS + kt * 8 + tig + 4];
            }
            #pragma unroll
            for (int j = 0; j < 4; j++) {
                int nc = (wc1 * 4 + j) * 8 + gid;
                bf[j][0] = rs[(kt * 8 + tig) * DP + nc];
                bf[j][1] = rs[(kt * 8 + tig + 4) * DP + nc];
            }
            #pragma unroll
            for (int i = 0; i < 2; i++)
                #pragma unroll
                for (int j = 0; j < 4; j++)
                    mma8(accT[i][j], af[i], bf[j]);
        }
    }

    // ---- store T (tf32): rows (m,a), cols d ----
    __syncthreads();
    #pragma unroll
    for (int i = 0; i < 2; i++)
        #pragma unroll
        for (int j = 0; j < 4; j++) {
            int r0 = (wr1 * 2 + i) * 16 + gid;
            int nc = (wc1 * 4 + j) * 8 + 2 * tig;
            uint2 lo = make_uint2(f2tf(accT[i][j][0]), f2tf(accT[i][j][1]));
            uint2 hi = make_uint2(f2tf(accT[i][j][2]), f2tf(accT[i][j][3]));
            *(uint2*)&ts[r0 * DP + nc]       = lo;
            *(uint2*)&ts[(r0 + 8) * DP + nc] = hi;
        }
    __syncthreads();   // T visible; x chunk (lnat alias) free to overwrite

    // ================= GEMM2 =================
    const int m   = w >> 2;           // 4 warps per m-row
    const int sw  = w & 3;
    const int wr2 = sw / GC2, wc2 = sw % GC2;
    float accY[2][4][4];
    #pragma unroll
    for (int i = 0; i < 2; i++)
        #pragma unroll
        for (int j = 0; j < 4; j++)
            #pragma unroll
            for (int q = 0; q < 4; q++) accY[i][j][q] = 0.0f;

    for (int ac = 0; ac < NC2; ac++) {
        if (ac) __syncthreads();   // protect lnat overwrite vs previous mma reads
        // ---- L chunk in NATIVE layout: lnat[a][b] = L[ac*32+a][b]/3, tf32 ----
        // float4 LDG (coalesced) + STS.128 (uniform banks) — conflict-free.
        #pragma unroll
        for (int u = 0; u < LN; u++) {
            int s = tid + u * THREADS;
            if (!LGUARD || s < 8 * B) {
                int a = s / (B / 4), b4 = s % (B / 4);
                float4 v = *(const float4*)&Lg[(ac * 32 + a) * B + b4 * 4];
                uint4 q = make_uint4(f2tf(v.x * (1.0f / 3.0f)),
                                     f2tf(v.y * (1.0f / 3.0f)),
                                     f2tf(v.z * (1.0f / 3.0f)),
                                     f2tf(v.w * (1.0f / 3.0f)));
                *(uint4*)&lnat[a * BS + b4 * 4] = q;
            }
        }
        __syncthreads();

        #pragma unroll
        for (int kt = 0; kt < 4; kt++) {
            uint32_t af[2][4], bf[4][2];
            #pragma unroll
            for (int i = 0; i < 2; i++) {
                int rbase = (wr2 * 2 + i) * 16 + gid;     // b index
                int c0 = kt * 8 + tig;                    // a index (lo)
                af[i][0] = lnat[c0 * BS + rbase];
                af[i][1] = lnat[c0 * BS + rbase + 8];
                af[i][2] = lnat[(c0 + 4) * BS + rbase];
                af[i][3] = lnat[(c0 + 4) * BS + rbase + 8];
            }
            #pragma unroll
            for (int j = 0; j < 4; j++) {
                int nc = (wc2 * 4 + j) * 8 + gid;
                bf[j][0] = ts[(m * A + ac * 32 + kt * 8 + tig) * DP + nc];
                bf[j][1] = ts[(m * A + ac * 32 + kt * 8 + tig + 4) * DP + nc];
            }
            #pragma unroll
            for (int i = 0; i < 2; i++)
                #pragma unroll
                for (int j = 0; j < 4; j++)
                    mma8(accY[i][j], af[i], bf[j]);
        }
    }

    // ---- RMW y (swizzled): per-thread disjoint within a factor ----
    #pragma unroll
    for (int i = 0; i < 2; i++)
        #pragma unroll
        for (int j = 0; j < 4; j++) {
            int b = (wr2 * 2 + i) * 16 + gid;
            int d = (wc2 * 4 + j) * 8 + 2 * tig;
            int n0 = b * D + d;
            int s0 = n0 + 2 * (n0 >> 5);
            float2 v0 = *(float2*)&ys[m * YS + s0];
            v0.x += accY[i][j][0]; v0.y += accY[i][j][1];
            *(float2*)&ys[m * YS + s0] = v0;
            int n2 = (b + 8) * D + d;
            int s2 = n2 + 2 * (n2 >> 5);
            float2 v2 = *(float2*)&ys[m * YS + s2];
            v2.x += accY[i][j][2]; v2.y += accY[i][j][3];
            *(float2*)&ys[m * YS + s2] = v2;
        }
}

__global__ __launch_bounds__(THREADS, 2) void klinear_kernel(
    const float* __restrict__ x,
    const float* __restrict__ L0, const float* __restrict__ R0,
    const float* __restrict__ L1, const float* __restrict__ R1,
    const float* __restrict__ L2, const float* __restrict__ R2,
    const float* __restrict__ bias,
    float* __restrict__ out)
{
    extern __shared__ float smem[];
    const int tid = threadIdx.x;
    const int m0  = blockIdx.x * MT;

    // zero y accumulator (bias added in epilogue)
    for (int i = tid; i < MT * YS; i += THREADS)
        smem[OFF_Y + i] = 0.0f;
    // (first factor's chunk-top __syncthreads orders this before any use)

    factor< 64,  64,  64,  64>(x, L0, R0, smem, m0, tid);
    factor< 32,  32, 128, 128>(x, L1, R1, smem, m0, tid);
    factor<128, 128,  32,  32>(x, L2, R2, smem, m0, tid);

    __syncthreads();

    // epilogue: y + bias -> out; thread owns n in [16*tid, 16*tid+16)
    const int n0 = tid * 16;
    #pragma unroll
    for (int h = 0; h < 2; h++) {
        int nb = n0 + h * 8;
        int s  = nb + 2 * (nb >> 5);   // constant shift within each 8-run
        float4 b0 = *(const float4*)&bias[nb];
        float4 b1 = *(const float4*)&bias[nb + 4];
        #pragma unroll
        for (int m = 0; m < MT; m++) {
            const float* yr = smem + OFF_Y + m * YS + s;
            float2 p0 = *(const float2*)&yr[0];
            float2 p1 = *(const float2*)&yr[2];
            float2 p2 = *(const float2*)&yr[4];
            float2 p3 = *(const float2*)&yr[6];
            float4 o0 = make_float4(p0.x + b0.x, p0.y + b0.y, p1.x + b0.z, p1.y + b0.w);
            float4 o1 = make_float4(p2.x + b1.x, p2.y + b1.y, p3.x + b1.z, p3.y + b1.w);
            *(float4*)&out[(size_t)(m0 + m) * NF + nb]     = o0;
            *(float4*)&out[(size_t)(m0 + m) * NF + nb + 4] = o1;
        }
    }
}

extern "C" void kernel_launch(void* const* d_in, const int* in_sizes, int n_in,
                              void* d_out, int out_size)
{
    const float* x    = (const float*)d_in[0];
    const float* L0   = (const float*)d_in[1];
    const float* R0   = (const float*)d_in[2];
    const float* L1   = (const float*)d_in[3];
    const float* R1   = (const float*)d_in[4];
    const float* L2   = (const float*)d_in[5];
    const float* R2   = (const float*)d_in[6];
    const float* bias = (const float*)d_in[7];
    float* out = (float*)d_out;

    static bool attr_set = false;
    if (!attr_set) {
        cudaFuncSetAttribute(klinear_kernel,
                             cudaFuncAttributeMaxDynamicSharedMemorySize, SMEM_BYTES);
        attr_set = true;
    }

    klinear_kernel<<<16384 / MT, THREADS, SMEM_BYTES>>>(
        x, L0, R0, L1, R1, L2, R2, bias, out);
}